// round 4
// baseline (speedup 1.0000x reference)
#include <cuda_runtime.h>
#include <cuda_fp16.h>
#include <cstdint>

#define DEPTH 4
#define B_    4096
#define H_    1024
#define K_    2048
#define N4H   4096

// ---------------- device scratch ----------------
__device__ __half g_A[DEPTH][B_][K_];    // [prev_out | s_h] fp16
__device__ __half g_W[DEPTH][K_][N4H];   // weights fp16 (input layout)
__device__ float  g_Z[B_][N4H];          // GEMM output scratch

// ---------------- helpers ----------------
__device__ __forceinline__ uint32_t smem_u32(const void* p) {
    uint32_t a;
    asm("{ .reg .u64 t; cvta.to.shared.u64 t, %1; cvt.u32.u64 %0, t; }" : "=r"(a) : "l"(p));
    return a;
}
__device__ __forceinline__ void cp16(uint32_t dst, const void* src) {
    asm volatile("cp.async.cg.shared.global [%0], [%1], 16;"
                 :: "r"(dst), "l"(__cvta_generic_to_global(src)));
}
__device__ __forceinline__ void ldsm4(uint32_t* r, uint32_t addr) {
    asm volatile("ldmatrix.sync.aligned.m8n8.x4.shared.b16 {%0,%1,%2,%3}, [%4];"
                 : "=r"(r[0]), "=r"(r[1]), "=r"(r[2]), "=r"(r[3]) : "r"(addr));
}
__device__ __forceinline__ void ldsm4t(uint32_t* r, uint32_t addr) {
    asm volatile("ldmatrix.sync.aligned.m8n8.x4.trans.shared.b16 {%0,%1,%2,%3}, [%4];"
                 : "=r"(r[0]), "=r"(r[1]), "=r"(r[2]), "=r"(r[3]) : "r"(addr));
}
__device__ __forceinline__ void mma16816(float* c, const uint32_t* a, const uint32_t* b) {
    asm volatile("mma.sync.aligned.m16n8k16.row.col.f32.f16.f16.f32 "
                 "{%0,%1,%2,%3}, {%4,%5,%6,%7}, {%8,%9}, {%0,%1,%2,%3};"
                 : "+f"(c[0]), "+f"(c[1]), "+f"(c[2]), "+f"(c[3])
                 : "r"(a[0]), "r"(a[1]), "r"(a[2]), "r"(a[3]), "r"(b[0]), "r"(b[1]));
}
__device__ __forceinline__ float sigm(float x) { return 1.0f / (1.0f + __expf(-x)); }

// ---------------- conversion / packing ----------------
__global__ void cvt_w(const float* __restrict__ W) {
    size_t i = (size_t)blockIdx.x * blockDim.x + threadIdx.x;   // one float4
    float4 v = ((const float4*)W)[i];
    __half2* dst = (__half2*)&g_W[0][0][0];
    dst[2 * i]     = __floats2half2_rn(v.x, v.y);
    dst[2 * i + 1] = __floats2half2_rn(v.z, v.w);
}
__global__ void pack_sh(const float* __restrict__ sh) {
    size_t i = (size_t)blockIdx.x * blockDim.x + threadIdx.x;
    size_t e = i * 4;
    size_t l = e / ((size_t)B_ * H_);
    size_t r = e % ((size_t)B_ * H_);
    size_t m = r >> 10, j = r & 1023;
    float4 v = ((const float4*)sh)[i];
    __half2* dst = (__half2*)&g_A[l][m][H_ + j];
    dst[0] = __floats2half2_rn(v.x, v.y);
    dst[1] = __floats2half2_rn(v.z, v.w);
}
__global__ void pack_x(const float* __restrict__ x) {
    size_t i = (size_t)blockIdx.x * blockDim.x + threadIdx.x;
    size_t e = i * 4;
    size_t m = e >> 10, j = e & 1023;
    float4 v = ((const float4*)x)[i];
    __half2* dst = (__half2*)&g_A[0][m][j];
    dst[0] = __floats2half2_rn(v.x, v.y);
    dst[1] = __floats2half2_rn(v.z, v.w);
}

// ---------------- GEMM: Z = A[l] @ W[l] ----------------
// BM=128, BN=256, BK=32, 3 stages, 256 threads (8 warps = 2m x 4n), warp 64x64.
#define BK      32
#define BN      256
#define ASTRIDE 80                 // bytes per A smem row (64 data + 16 pad)
#define BSTRIDE 528                // bytes per B smem row (512 data + 16 pad)
#define A_STG   (128 * ASTRIDE)    // 10240
#define B_STG   (BK * BSTRIDE)     // 16896
#define STG     (A_STG + B_STG)    // 27136
#define NSTAGE  3
#define SMEM_G  (NSTAGE * STG)     // 81408

__global__ void __launch_bounds__(256, 1)
gemm_kernel(int layer) {
    extern __shared__ __align__(16) char smem[];
    const uint32_t sbase = smem_u32(smem);

    const int tid = threadIdx.x;
    const int wid = tid >> 5, lane = tid & 31;
    const int m0 = blockIdx.y * 128, n0 = blockIdx.x * BN;
    const int wm = (wid >> 2) * 64, wn = (wid & 3) * 64;

    const __half* Ag = &g_A[layer][0][0];
    const __half* Wg = &g_W[layer][0][0];

    // load coords: A 128 rows x 4 chunks (2/thread); B 32 rows x 32 chunks (4/thread)
    const int ar = tid >> 1, ac = (tid & 1) * 2;
    const int br = tid >> 3, bc = (tid & 7) * 4;

    auto load_stage = [&](int s, int k0) {
        uint32_t da = sbase + s * STG;
        uint32_t db = da + A_STG;
        cp16(da + ar * ASTRIDE + ac * 16,       Ag + (size_t)(m0 + ar) * K_ + k0 + ac * 8);
        cp16(da + ar * ASTRIDE + (ac + 1) * 16, Ag + (size_t)(m0 + ar) * K_ + k0 + (ac + 1) * 8);
        #pragma unroll
        for (int q = 0; q < 4; ++q)
            cp16(db + br * BSTRIDE + (bc + q) * 16,
                 Wg + (size_t)(k0 + br) * N4H + n0 + (bc + q) * 8);
        asm volatile("cp.async.commit_group;" ::: "memory");
    };

    float acc[4][8][4];
    #pragma unroll
    for (int i = 0; i < 4; ++i)
        #pragma unroll
        for (int j = 0; j < 8; ++j)
            #pragma unroll
            for (int q = 0; q < 4; ++q) acc[i][j][q] = 0.f;

    load_stage(0, 0);
    load_stage(1, BK);

    const int NIT = K_ / BK;  // 64
    for (int kt = 0; kt < NIT; ++kt) {
        // make stage kt ready
        if (kt < NIT - 1) asm volatile("cp.async.wait_group 1;" ::: "memory");
        else              asm volatile("cp.async.wait_group 0;" ::: "memory");
        __syncthreads();

        // prefetch stage kt+2 (overwrites stage computed at kt-1; sync above guards it)
        if (kt + 2 < NIT) load_stage((kt + 2) % NSTAGE, (kt + 2) * BK);

        const uint32_t da = sbase + (kt % NSTAGE) * STG;
        const uint32_t db = da + A_STG;
        #pragma unroll
        for (int k16 = 0; k16 < 2; ++k16) {
            uint32_t af[4][4], bf[4][4];
            #pragma unroll
            for (int mf = 0; mf < 4; ++mf)
                ldsm4(af[mf], da + (wm + mf * 16 + (lane & 15)) * ASTRIDE
                                 + k16 * 32 + (lane >> 4) * 16);
            #pragma unroll
            for (int ns = 0; ns < 4; ++ns)
                ldsm4t(bf[ns], db + (k16 * 16 + (lane & 15)) * BSTRIDE
                                  + (wn + ns * 16 + (lane >> 4) * 8) * 2);
            #pragma unroll
            for (int mf = 0; mf < 4; ++mf)
                #pragma unroll
                for (int nf = 0; nf < 8; ++nf)
                    mma16816(acc[mf][nf], af[mf], &bf[nf >> 1][(nf & 1) * 2]);
        }
    }

    // epilogue
    const int rr = lane >> 2, cc = (lane & 3) * 2;
    #pragma unroll
    for (int mf = 0; mf < 4; ++mf)
        #pragma unroll
        for (int nf = 0; nf < 8; ++nf) {
            int r = m0 + wm + mf * 16 + rr;
            int c = n0 + wn + nf * 8 + cc;
            *(float2*)&g_Z[r][c]     = make_float2(acc[mf][nf][0], acc[mf][nf][1]);
            *(float2*)&g_Z[r + 8][c] = make_float2(acc[mf][nf][2], acc[mf][nf][3]);
        }
}

// ---------------- pointwise LSTM gates ----------------
__global__ void lstm_pw(int layer, const float* __restrict__ bias,
                        const float* __restrict__ c_in,
                        float* __restrict__ h_out, float* __restrict__ c_out,
                        float* __restrict__ final_out) {
    size_t i = (size_t)blockIdx.x * blockDim.x + threadIdx.x;  // one float4
    int m = (int)(i >> 8);
    int j = (int)((i & 255) * 4);
    float4 zi = *(const float4*)&g_Z[m][j];
    float4 zf = *(const float4*)&g_Z[m][1024 + j];
    float4 zo = *(const float4*)&g_Z[m][2048 + j];
    float4 zg = *(const float4*)&g_Z[m][3072 + j];
    float4 bi = *(const float4*)&bias[j];
    float4 bf = *(const float4*)&bias[1024 + j];
    float4 bo = *(const float4*)&bias[2048 + j];
    float4 bg = *(const float4*)&bias[3072 + j];
    float4 cv = *(const float4*)&c_in[(size_t)m * H_ + j];

    float zin[4] = {zi.x + bi.x, zi.y + bi.y, zi.z + bi.z, zi.w + bi.w};
    float zfn[4] = {zf.x + bf.x, zf.y + bf.y, zf.z + bf.z, zf.w + bf.w};
    float zon[4] = {zo.x + bo.x, zo.y + bo.y, zo.z + bo.z, zo.w + bo.w};
    float zgn[4] = {zg.x + bg.x, zg.y + bg.y, zg.z + bg.z, zg.w + bg.w};
    float co[4] = {cv.x, cv.y, cv.z, cv.w};
    float hb[4], cb[4];
    #pragma unroll
    for (int t = 0; t < 4; ++t) {
        float ig = sigm(zin[t]);
        float fg = sigm(zfn[t]);
        float og = sigm(zon[t]);
        float gg = tanhf(zgn[t]);
        float cn = co[t] * fg + gg * ig;
        cb[t] = cn;
        hb[t] = tanhf(cn) * og;
    }
    size_t off = (size_t)m * H_ + j;
    *(float4*)&h_out[off] = make_float4(hb[0], hb[1], hb[2], hb[3]);
    *(float4*)&c_out[off] = make_float4(cb[0], cb[1], cb[2], cb[3]);
    if (layer + 1 < DEPTH) {
        __half2* an = (__half2*)&g_A[layer + 1][m][j];
        an[0] = __floats2half2_rn(hb[0], hb[1]);
        an[1] = __floats2half2_rn(hb[2], hb[3]);
    }
    if (final_out)
        *(float4*)&final_out[off] = make_float4(hb[0], hb[1], hb[2], hb[3]);
}

// ---------------- launch ----------------
extern "C" void kernel_launch(void* const* d_in, const int* in_sizes, int n_in,
                              void* d_out, int out_size) {
    const float* x  = (const float*)d_in[0];
    const float* sh = (const float*)d_in[1];
    const float* sc = (const float*)d_in[2];
    const float* W  = (const float*)d_in[3];
    const float* b  = (const float*)d_in[4];
    float* out = (float*)d_out;

    const size_t BH = (size_t)B_ * H_;
    float* out_final = out;
    float* out_h     = out + BH;
    float* out_c     = out + BH + DEPTH * BH;

    cudaFuncSetAttribute(gemm_kernel, cudaFuncAttributeMaxDynamicSharedMemorySize, SMEM_G);

    cvt_w<<<(DEPTH * (size_t)K_ * N4H / 4) / 256, 256>>>(W);
    pack_sh<<<(DEPTH * BH / 4) / 256, 256>>>(sh);
    pack_x<<<(BH / 4) / 256, 256>>>(x);

    for (int l = 0; l < DEPTH; ++l) {
        gemm_kernel<<<dim3(N4H / BN, B_ / 128), 256, SMEM_G>>>(l);
        lstm_pw<<<(BH / 4) / 256, 256>>>(
            l, b + (size_t)l * N4H, sc + (size_t)l * BH,
            out_h + (size_t)l * BH, out_c + (size_t)l * BH,
            (l == DEPTH - 1) ? out_final : nullptr);
    }
}

// round 5
// speedup vs baseline: 1.3900x; 1.3900x over previous
#include <cuda_runtime.h>
#include <cuda_fp16.h>
#include <cstdint>

#define DEPTH 4
#define B_    4096
#define H_    1024
#define K_    2048
#define N4H   4096

// ---------------- device scratch ----------------
__device__ __half g_A[DEPTH][B_][K_];    // [prev_out | s_h] fp16
__device__ __half g_W[DEPTH][K_][N4H];   // weights fp16 (input layout)
__device__ float  g_Z[B_][N4H];          // GEMM output scratch

// ---------------- helpers ----------------
__device__ __forceinline__ uint32_t smem_u32(const void* p) {
    uint32_t a;
    asm("{ .reg .u64 t; cvta.to.shared.u64 t, %1; cvt.u32.u64 %0, t; }" : "=r"(a) : "l"(p));
    return a;
}
__device__ __forceinline__ void cp16(uint32_t dst, const void* src) {
    asm volatile("cp.async.cg.shared.global [%0], [%1], 16;"
                 :: "r"(dst), "l"(__cvta_generic_to_global(src)));
}
__device__ __forceinline__ void ldsm4(uint32_t* r, uint32_t addr) {
    asm volatile("ldmatrix.sync.aligned.m8n8.x4.shared.b16 {%0,%1,%2,%3}, [%4];"
                 : "=r"(r[0]), "=r"(r[1]), "=r"(r[2]), "=r"(r[3]) : "r"(addr));
}
__device__ __forceinline__ void ldsm4t(uint32_t* r, uint32_t addr) {
    asm volatile("ldmatrix.sync.aligned.m8n8.x4.trans.shared.b16 {%0,%1,%2,%3}, [%4];"
                 : "=r"(r[0]), "=r"(r[1]), "=r"(r[2]), "=r"(r[3]) : "r"(addr));
}
__device__ __forceinline__ void mma16816(float* c, const uint32_t* a, const uint32_t* b) {
    asm volatile("mma.sync.aligned.m16n8k16.row.col.f32.f16.f16.f32 "
                 "{%0,%1,%2,%3}, {%4,%5,%6,%7}, {%8,%9}, {%0,%1,%2,%3};"
                 : "+f"(c[0]), "+f"(c[1]), "+f"(c[2]), "+f"(c[3])
                 : "r"(a[0]), "r"(a[1]), "r"(a[2]), "r"(a[3]), "r"(b[0]), "r"(b[1]));
}
__device__ __forceinline__ float sigm(float x) { return 1.0f / (1.0f + __expf(-x)); }

// ---------------- conversion / packing ----------------
__global__ void cvt_w(const float* __restrict__ W) {
    size_t i = (size_t)blockIdx.x * blockDim.x + threadIdx.x;   // one float4
    float4 v = ((const float4*)W)[i];
    __half2* dst = (__half2*)&g_W[0][0][0];
    dst[2 * i]     = __floats2half2_rn(v.x, v.y);
    dst[2 * i + 1] = __floats2half2_rn(v.z, v.w);
}
__global__ void pack_sh(const float* __restrict__ sh) {
    size_t i = (size_t)blockIdx.x * blockDim.x + threadIdx.x;
    size_t e = i * 4;
    size_t l = e / ((size_t)B_ * H_);
    size_t r = e % ((size_t)B_ * H_);
    size_t m = r >> 10, j = r & 1023;
    float4 v = ((const float4*)sh)[i];
    __half2* dst = (__half2*)&g_A[l][m][H_ + j];
    dst[0] = __floats2half2_rn(v.x, v.y);
    dst[1] = __floats2half2_rn(v.z, v.w);
}
__global__ void pack_x(const float* __restrict__ x) {
    size_t i = (size_t)blockIdx.x * blockDim.x + threadIdx.x;
    size_t e = i * 4;
    size_t m = e >> 10, j = e & 1023;
    float4 v = ((const float4*)x)[i];
    __half2* dst = (__half2*)&g_A[0][m][j];
    dst[0] = __floats2half2_rn(v.x, v.y);
    dst[1] = __floats2half2_rn(v.z, v.w);
}

// ---------------- GEMM: Z = A[l] @ W[l] ----------------
// BM=128, BN=128, BK=32, 3 stages, 1 sync/iter, 256 thr (8 warps = 2m x 4n),
// warp tile 64x32, 2 CTAs/SM.
#define BK      32
#define ASTRIDE 80                 // bytes per A smem row (64 data + 16 pad)
#define BSTRIDE 272                // bytes per B smem row (256 data + 16 pad)
#define A_STG   (128 * ASTRIDE)    // 10240
#define B_STG   (BK * BSTRIDE)     // 8704
#define STG     (A_STG + B_STG)    // 18944
#define NSTAGE  3
#define SMEM_G  (NSTAGE * STG)     // 56832

__global__ void __launch_bounds__(256, 2)
gemm_kernel(int layer) {
    extern __shared__ __align__(16) char smem[];
    const uint32_t sbase = smem_u32(smem);

    const int tid = threadIdx.x;
    const int wid = tid >> 5, lane = tid & 31;
    const int m0 = blockIdx.y * 128, n0 = blockIdx.x * 128;
    const int wm = (wid >> 2) * 64, wn = (wid & 3) * 32;

    const __half* Ag = &g_A[layer][0][0];
    const __half* Wg = &g_W[layer][0][0];

    // load coords: A 128 rows x 4 chunks (2/thread); B 32 rows x 16 chunks (2/thread)
    const int ar = tid >> 1, ac = (tid & 1) * 2;
    const int br = tid >> 4, bc = tid & 15;

    auto load_stage = [&](int s, int k0) {
        uint32_t da = sbase + s * STG;
        uint32_t db = da + A_STG;
        cp16(da + ar * ASTRIDE + ac * 16,       Ag + (size_t)(m0 + ar) * K_ + k0 + ac * 8);
        cp16(da + ar * ASTRIDE + (ac + 1) * 16, Ag + (size_t)(m0 + ar) * K_ + k0 + (ac + 1) * 8);
        cp16(db + br * BSTRIDE + bc * 16,        Wg + (size_t)(k0 + br) * N4H + n0 + bc * 8);
        cp16(db + (br + 16) * BSTRIDE + bc * 16, Wg + (size_t)(k0 + br + 16) * N4H + n0 + bc * 8);
        asm volatile("cp.async.commit_group;" ::: "memory");
    };

    float acc[4][4][4];
    #pragma unroll
    for (int i = 0; i < 4; ++i)
        #pragma unroll
        for (int j = 0; j < 4; ++j)
            #pragma unroll
            for (int q = 0; q < 4; ++q) acc[i][j][q] = 0.f;

    load_stage(0, 0);
    load_stage(1, BK);

    const int NIT = K_ / BK;  // 64
    for (int kt = 0; kt < NIT; ++kt) {
        // stage kt ready (all but newest group complete)
        if (kt + 1 < NIT) asm volatile("cp.async.wait_group 1;" ::: "memory");
        else              asm volatile("cp.async.wait_group 0;" ::: "memory");
        __syncthreads();

        // prefetch stage kt+2 into slot of stage kt-1 (reads done before this barrier)
        if (kt + 2 < NIT) load_stage((kt + 2) % NSTAGE, (kt + 2) * BK);

        const uint32_t da = sbase + (kt % NSTAGE) * STG;
        const uint32_t db = da + A_STG;
        #pragma unroll
        for (int k16 = 0; k16 < 2; ++k16) {
            uint32_t af[4][4], bf[2][4];
            #pragma unroll
            for (int mf = 0; mf < 4; ++mf)
                ldsm4(af[mf], da + (wm + mf * 16 + (lane & 15)) * ASTRIDE
                                 + k16 * 32 + (lane >> 4) * 16);
            #pragma unroll
            for (int ns = 0; ns < 2; ++ns)
                ldsm4t(bf[ns], db + (k16 * 16 + (lane & 15)) * BSTRIDE
                                  + (wn + ns * 16 + (lane >> 4) * 8) * 2);
            #pragma unroll
            for (int mf = 0; mf < 4; ++mf)
                #pragma unroll
                for (int nf = 0; nf < 4; ++nf)
                    mma16816(acc[mf][nf], af[mf], &bf[nf >> 1][(nf & 1) * 2]);
        }
    }

    // epilogue
    const int rr = lane >> 2, cc = (lane & 3) * 2;
    #pragma unroll
    for (int mf = 0; mf < 4; ++mf)
        #pragma unroll
        for (int nf = 0; nf < 4; ++nf) {
            int r = m0 + wm + mf * 16 + rr;
            int c = n0 + wn + nf * 8 + cc;
            *(float2*)&g_Z[r][c]     = make_float2(acc[mf][nf][0], acc[mf][nf][1]);
            *(float2*)&g_Z[r + 8][c] = make_float2(acc[mf][nf][2], acc[mf][nf][3]);
        }
}

// ---------------- pointwise LSTM gates ----------------
__global__ void lstm_pw(int layer, const float* __restrict__ bias,
                        const float* __restrict__ c_in,
                        float* __restrict__ h_out, float* __restrict__ c_out,
                        float* __restrict__ final_out) {
    size_t i = (size_t)blockIdx.x * blockDim.x + threadIdx.x;  // one float4
    int m = (int)(i >> 8);
    int j = (int)((i & 255) * 4);
    float4 zi = *(const float4*)&g_Z[m][j];
    float4 zf = *(const float4*)&g_Z[m][1024 + j];
    float4 zo = *(const float4*)&g_Z[m][2048 + j];
    float4 zg = *(const float4*)&g_Z[m][3072 + j];
    float4 bi = *(const float4*)&bias[j];
    float4 bf = *(const float4*)&bias[1024 + j];
    float4 bo = *(const float4*)&bias[2048 + j];
    float4 bg = *(const float4*)&bias[3072 + j];
    float4 cv = *(const float4*)&c_in[(size_t)m * H_ + j];

    float zin[4] = {zi.x + bi.x, zi.y + bi.y, zi.z + bi.z, zi.w + bi.w};
    float zfn[4] = {zf.x + bf.x, zf.y + bf.y, zf.z + bf.z, zf.w + bf.w};
    float zon[4] = {zo.x + bo.x, zo.y + bo.y, zo.z + bo.z, zo.w + bo.w};
    float zgn[4] = {zg.x + bg.x, zg.y + bg.y, zg.z + bg.z, zg.w + bg.w};
    float co[4] = {cv.x, cv.y, cv.z, cv.w};
    float hb[4], cb[4];
    #pragma unroll
    for (int t = 0; t < 4; ++t) {
        float ig = sigm(zin[t]);
        float fg = sigm(zfn[t]);
        float og = sigm(zon[t]);
        float gg = tanhf(zgn[t]);
        float cn = co[t] * fg + gg * ig;
        cb[t] = cn;
        hb[t] = tanhf(cn) * og;
    }
    size_t off = (size_t)m * H_ + j;
    *(float4*)&h_out[off] = make_float4(hb[0], hb[1], hb[2], hb[3]);
    *(float4*)&c_out[off] = make_float4(cb[0], cb[1], cb[2], cb[3]);
    if (layer + 1 < DEPTH) {
        __half2* an = (__half2*)&g_A[layer + 1][m][j];
        an[0] = __floats2half2_rn(hb[0], hb[1]);
        an[1] = __floats2half2_rn(hb[2], hb[3]);
    }
    if (final_out)
        *(float4*)&final_out[off] = make_float4(hb[0], hb[1], hb[2], hb[3]);
}

// ---------------- launch ----------------
extern "C" void kernel_launch(void* const* d_in, const int* in_sizes, int n_in,
                              void* d_out, int out_size) {
    const float* x  = (const float*)d_in[0];
    const float* sh = (const float*)d_in[1];
    const float* sc = (const float*)d_in[2];
    const float* W  = (const float*)d_in[3];
    const float* b  = (const float*)d_in[4];
    float* out = (float*)d_out;

    const size_t BH = (size_t)B_ * H_;
    float* out_final = out;
    float* out_h     = out + BH;
    float* out_c     = out + BH + DEPTH * BH;

    cudaFuncSetAttribute(gemm_kernel, cudaFuncAttributeMaxDynamicSharedMemorySize, SMEM_G);

    cvt_w<<<(DEPTH * (size_t)K_ * N4H / 4) / 256, 256>>>(W);
    pack_sh<<<(DEPTH * BH / 4) / 256, 256>>>(sh);
    pack_x<<<(BH / 4) / 256, 256>>>(x);

    for (int l = 0; l < DEPTH; ++l) {
        gemm_kernel<<<dim3(N4H / 128, B_ / 128), 256, SMEM_G>>>(l);
        lstm_pw<<<(BH / 4) / 256, 256>>>(
            l, b + (size_t)l * N4H, sc + (size_t)l * BH,
            out_h + (size_t)l * BH, out_c + (size_t)l * BH,
            (l == DEPTH - 1) ? out_final : nullptr);
    }
}